// round 16
// baseline (speedup 1.0000x reference)
#include <cuda_runtime.h>
#include <cuda_bf16.h>
#include <math.h>
#include <stdint.h>

#define DIM   512
#define N_ELEM (DIM*DIM)       // 262144
#define KFLAT 1024             // DT*2
#define NB    128              // persistent CTAs (1/SM)
#define NTH   256

// ---------------- device state ----------------
__device__ float g_Y[2][N_ELEM];       // y double buffer
__device__ float g_K[7][2][N_ELEM];    // k arrays, split-K=2 partials
__device__ __align__(16) __nv_bfloat16 g_bhi[N_ELEM*2];  // basis hi [row][j*2+k]
__device__ __align__(16) __nv_bfloat16 g_blo[N_ELEM*2];  // basis lo
__device__ __align__(16) __nv_bfloat16 g_Chi[DIM*KFLAT]; // C hi (row=out col, K contiguous)
__device__ __align__(16) __nv_bfloat16 g_Clo[DIM*KFLAT]; // C lo
__device__ float g_red[5*NB];
__device__ int   g_flags[NB];
__device__ int   g_yfin;

// Dormand-Prince tables
__constant__ float STG_C[8][6] = {
  {0.f,0.f,0.f,0.f,0.f,0.f},
  {1.f,0.f,0.f,0.f,0.f,0.f},
  {0.2f,0.f,0.f,0.f,0.f,0.f},
  {3.f/40.f, 9.f/40.f, 0.f,0.f,0.f,0.f},
  {44.f/45.f, -56.f/15.f, 32.f/9.f, 0.f,0.f,0.f},
  {19372.f/6561.f, -25360.f/2187.f, 64448.f/6561.f, -212.f/729.f,0.f,0.f},
  {9017.f/3168.f, -355.f/33.f, 46732.f/5247.f, 49.f/176.f, -5103.f/18656.f, 0.f},
  {35.f/384.f, 0.f, 500.f/1113.f, 125.f/192.f, -2187.f/6784.f, 11.f/84.f},
};
__constant__ float STG_T[8] = {0.f, 1.f, 0.2f, 0.3f, 0.8f, 8.f/9.f, 1.f, 1.f};
__constant__ float ERR_C[6] = { 71.f/57600.f, -71.f/16695.f, 71.f/1920.f,
                                -17253.f/339200.f, 22.f/525.f, -1.f/40.f };

#define SWZ128(o) ((o) ^ (((o) >> 3) & 0x70))

__device__ __forceinline__ uint32_t smem_u32(const void* p) {
  uint32_t a;
  asm("{ .reg .u64 t; cvta.to.shared.u64 t, %1; cvt.u32.u64 %0, t; }" : "=r"(a) : "l"(p));
  return a;
}

// ---------------- flag-array grid barrier (parallel arrive + poll) ----------
__device__ __forceinline__ void gridbar(int e, int id) {
  __syncthreads();
  if (threadIdx.x == 0) {
    __threadfence();                    // data visible in L2 before flag
    atomicExch(&g_flags[id], e);        // parallel arrival, no serialization
  }
  if (threadIdx.x < NB) {
    while (__ldcg(&g_flags[threadIdx.x]) < e) { }
  }
  __syncthreads();
}

// ---------------- basis pack helper ----------------
__device__ __forceinline__ void basis_pack(float ph, uint32_t& h, uint32_t& l) {
  float s, c;
  sincosf(ph, &s, &c);
  __nv_bfloat16 sh = __float2bfloat16(s);
  __nv_bfloat16 ch = __float2bfloat16(c);
  __nv_bfloat162 hp(sh, ch);
  __nv_bfloat162 lp(__float2bfloat16(s - __bfloat162float(sh)),
                    __float2bfloat16(c - __bfloat162float(ch)));
  h = *(uint32_t*)&hp;
  l = *(uint32_t*)&lp;
}

// sum of split partials, vectorized
__device__ __forceinline__ float4 ksum2(int kidx, int v) {
  float4 a = __ldcg(&((const float4*)g_K[kidx][0])[v]);
  float4 b = __ldcg(&((const float4*)g_K[kidx][1])[v]);
  return make_float4(a.x + b.x, a.y + b.y, a.z + b.z, a.w + b.w);
}

// ---------------- vectorized stage — EXACT R10/R13 arithmetic ---------------
// acc += c_j * (split0 + split1)   (ADD then FMA, j in order) — this exact
// association is what keeps the adaptive trajectory at ~2 steps.
template<int SID, int NK, int WRITEY>
__device__ __forceinline__ void stage_v(float hs, float t, int ycur, int i1, int v) {
  float ts = t + STG_T[SID] * hs;
  float4 y4 = __ldcg(&((const float4*)g_Y[ycur])[v]);
  float ax = 0.f, ay = 0.f, az = 0.f, aw = 0.f;
  #pragma unroll
  for (int j = 0; j < NK; j++) {
    int kidx = (j == 0) ? i1 : j;
    float cj = STG_C[SID][j];
    float4 k0 = __ldcg(&((const float4*)g_K[kidx][0])[v]);
    float4 k1 = __ldcg(&((const float4*)g_K[kidx][1])[v]);
    ax += cj * (k0.x + k1.x);
    ay += cj * (k0.y + k1.y);
    az += cj * (k0.z + k1.z);
    aw += cj * (k0.w + k1.w);
  }
  float yt0 = y4.x, yt1 = y4.y, yt2 = y4.z, yt3 = y4.w;
  if (NK > 0) { yt0 += hs * ax; yt1 += hs * ay; yt2 += hs * az; yt3 += hs * aw; }
  if (WRITEY) ((float4*)g_Y[ycur ^ 1])[v] = make_float4(yt0, yt1, yt2, yt3);
  uint4 H, L;
  basis_pack(yt0 + ts, H.x, L.x);
  basis_pack(yt1 + ts, H.y, L.y);
  basis_pack(yt2 + ts, H.z, L.z);
  basis_pack(yt3 + ts, H.w, L.w);
  ((uint4*)g_bhi)[v] = H;
  ((uint4*)g_blo)[v] = L;
}

template<int SID, int NK, int WRITEY>
__device__ __forceinline__ void stage_t(float hs, float t, int ycur, int i1, int v0) {
  stage_v<SID, NK, WRITEY>(hs, t, ycur, i1, v0);
  stage_v<SID, NK, WRITEY>(hs, t, ycur, i1, v0 + NTH);
}

// ---------------- bf16 mma GEMM NT (round-10 champion, verbatim logic) ------
__device__ __forceinline__ void mma_bf16(float* c, uint32_t a0, uint32_t a1,
                                         uint32_t a2, uint32_t a3,
                                         uint32_t b0, uint32_t b1) {
  asm volatile("mma.sync.aligned.m16n8k16.row.col.f32.bf16.bf16.f32 "
               "{%0,%1,%2,%3}, {%4,%5,%6,%7}, {%8,%9}, {%0,%1,%2,%3};"
               : "+f"(c[0]), "+f"(c[1]), "+f"(c[2]), "+f"(c[3])
               : "r"(a0), "r"(a1), "r"(a2), "r"(a3), "r"(b0), "r"(b1));
}

#define TILE_B 8192   // 64 rows x 128 bytes

__device__ void gemm_feval(int dst, int row0, int col0, int kbase, int bz,
                           char* AsBuf, char* BsBuf) {
  float* D = &g_K[dst][bz][0];
  int tid = threadIdx.x, wid = tid >> 5, lane = tid & 31;
  int wr = wid >> 2, wc = wid & 3;         // warp grid 2x4: tile 32x16

  int lrow0 = tid >> 3, lch0 = tid & 7;
  int c1i = tid + 256;
  int lrow1 = c1i >> 3, lch1 = c1i & 7;
  uint32_t so0 = SWZ128((uint32_t)(lrow0 * 128 + lch0 * 16));
  uint32_t so1 = SWZ128((uint32_t)(lrow1 * 128 + lch1 * 16));

  int g = lane >> 3, r = lane & 7;
  int a_m = ((g & 1) ? 8 : 0) + r;
  int a_k = (g >> 1) * 8;
  int b_n = ((g >> 1) ? 8 : 0) + r;
  int b_k = (g & 1) * 8;

  uint32_t Asm = smem_u32(AsBuf), Bsm = smem_u32(BsBuf);
  float acc[2][2][4] = {};

  // prologue: chunk 0 -> buffer 0
  {
    const __nv_bfloat16* As = g_bhi;
    const __nv_bfloat16* Bs = g_Chi;
    *(uint4*)(AsBuf + so0) = __ldcg((const uint4*)&As[(size_t)(row0 + lrow0) * KFLAT + kbase + lch0 * 8]);
    *(uint4*)(AsBuf + so1) = __ldcg((const uint4*)&As[(size_t)(row0 + lrow1) * KFLAT + kbase + lch1 * 8]);
    *(uint4*)(BsBuf + so0) = __ldcg((const uint4*)&Bs[(size_t)(col0 + lrow0) * KFLAT + kbase + lch0 * 8]);
    *(uint4*)(BsBuf + so1) = __ldcg((const uint4*)&Bs[(size_t)(col0 + lrow1) * KFLAT + kbase + lch1 * 8]);
  }
  __syncthreads();

  int cur = 0;
  for (int tk = 0; tk < 24; tk++) {
    uint4 av0, av1, bv0, bv1;
    if (tk < 23) {
      int nt = tk + 1, seg = nt >> 3;
      const __nv_bfloat16* As = (seg == 2) ? g_blo : g_bhi;
      const __nv_bfloat16* Bs = (seg == 1) ? g_Clo : g_Chi;
      int koff = kbase + (nt & 7) * 64;
      av0 = __ldcg((const uint4*)&As[(size_t)(row0 + lrow0) * KFLAT + koff + lch0 * 8]);
      av1 = __ldcg((const uint4*)&As[(size_t)(row0 + lrow1) * KFLAT + koff + lch1 * 8]);
      bv0 = __ldcg((const uint4*)&Bs[(size_t)(col0 + lrow0) * KFLAT + koff + lch0 * 8]);
      bv1 = __ldcg((const uint4*)&Bs[(size_t)(col0 + lrow1) * KFLAT + koff + lch1 * 8]);
    }
    uint32_t Ab = Asm + cur * TILE_B, Bb = Bsm + cur * TILE_B;
    #pragma unroll
    for (int s = 0; s < 4; s++) {
      uint32_t b0, b1, b2, b3;
      uint32_t addrB = Bb + SWZ128((uint32_t)((wc * 16 + b_n) * 128 + (s * 16 + b_k) * 2));
      asm volatile("ldmatrix.sync.aligned.m8n8.x4.shared.b16 {%0,%1,%2,%3}, [%4];"
                   : "=r"(b0), "=r"(b1), "=r"(b2), "=r"(b3) : "r"(addrB));
      #pragma unroll
      for (int mf = 0; mf < 2; mf++) {
        uint32_t a0, a1, a2, a3;
        uint32_t addrA = Ab + SWZ128((uint32_t)((wr * 32 + mf * 16 + a_m) * 128 + (s * 16 + a_k) * 2));
        asm volatile("ldmatrix.sync.aligned.m8n8.x4.shared.b16 {%0,%1,%2,%3}, [%4];"
                     : "=r"(a0), "=r"(a1), "=r"(a2), "=r"(a3) : "r"(addrA));
        mma_bf16(acc[mf][0], a0, a1, a2, a3, b0, b1);
        mma_bf16(acc[mf][1], a0, a1, a2, a3, b2, b3);
      }
    }
    if (tk < 23) {
      int nxt = cur ^ 1;
      *(uint4*)(AsBuf + nxt * TILE_B + so0) = av0;
      *(uint4*)(AsBuf + nxt * TILE_B + so1) = av1;
      *(uint4*)(BsBuf + nxt * TILE_B + so0) = bv0;
      *(uint4*)(BsBuf + nxt * TILE_B + so1) = bv1;
      __syncthreads();
      cur = nxt;
    }
  }

  int mrow = row0 + wr * 32 + (lane >> 2);
  int ncol = col0 + wc * 16 + (lane & 3) * 2;
  #pragma unroll
  for (int mf = 0; mf < 2; mf++) {
    #pragma unroll
    for (int nf = 0; nf < 2; nf++) {
      float2 lo = {acc[mf][nf][0], acc[mf][nf][1]};
      float2 hi = {acc[mf][nf][2], acc[mf][nf][3]};
      *(float2*)&D[(size_t)(mrow + mf * 16)     * DIM + ncol + nf * 8] = lo;
      *(float2*)&D[(size_t)(mrow + mf * 16 + 8) * DIM + ncol + nf * 8] = hi;
    }
  }
  __syncthreads();
}

// ---------------- block reduce ----------------
__device__ __forceinline__ float blockReduce(float v, float* sh) {
  int tid = threadIdx.x;
  sh[tid] = v; __syncthreads();
  for (int s = 128; s > 0; s >>= 1) {
    if (tid < s) sh[tid] += sh[tid + s];
    __syncthreads();
  }
  float r = sh[0];
  __syncthreads();
  return r;
}

__device__ __forceinline__ float gridSum(int slot) {
  float S = 0.f;
  for (int b = 0; b < NB; b++) S += __ldcg(&g_red[slot * NB + b]);
  return S;
}

// squared scaled norm of one float4 pair (y, f)
__device__ __forceinline__ void norm_acc(float4 y4, float4 f4, float& s0, float& s1) {
  float yy[4] = {y4.x, y4.y, y4.z, y4.w};
  float ff[4] = {f4.x, f4.y, f4.z, f4.w};
  #pragma unroll
  for (int e = 0; e < 4; e++) {
    float sc = 1e-6f + 1e-3f * fabsf(yy[e]);
    float a = yy[e] / sc, b = ff[e] / sc;
    s0 += a * a; s1 += b * b;
  }
}

// ---------------- persistent ODE kernel ----------------
__global__ __launch_bounds__(NTH, 1) void k_ode() {
  __shared__ __align__(16) char AsBuf[2 * TILE_B];
  __shared__ __align__(16) char BsBuf[2 * TILE_B];
  __shared__ float sred[NTH];
  int tid = threadIdx.x, id = blockIdx.x;
  int bx = id & 7, by = (id >> 3) & 7, bz = id >> 6;
  int row0 = by * 64, col0 = bx * 64, kbase = bz * 512;
  int v0 = id * 512 + tid;        // this thread's two float4s: v0, v0+256
  int ep = 0;

  int ycur = 0, i1 = 0, i7 = 6;

  // ---- f0 = f(0, y0) -> k[i1] ----
  stage_t<0, 0, 0>(0.f, 0.f, ycur, i1, v0);
  gridbar(++ep, id);
  gemm_feval(i1, row0, col0, kbase, bz, AsBuf, BsBuf);
  gridbar(++ep, id);

  // ---- d0, d1 ----
  {
    float s0 = 0.f, s1 = 0.f;
    #pragma unroll
    for (int q = 0; q < 2; q++) {
      int v = v0 + q * NTH;
      float4 y4 = __ldcg(&((const float4*)g_Y[ycur])[v]);
      float4 f4 = ksum2(i1, v);
      norm_acc(y4, f4, s0, s1);
    }
    float S0 = blockReduce(s0, sred);
    float S1 = blockReduce(s1, sred);
    if (tid == 0) { g_red[0 * NB + id] = S0; g_red[1 * NB + id] = S1; }
  }
  gridbar(++ep, id);
  float d0 = sqrtf(gridSum(0) / (float)N_ELEM);
  float d1 = sqrtf(gridSum(1) / (float)N_ELEM);
  float h0 = (d0 < 1e-5f || d1 < 1e-5f) ? 1e-6f : 0.01f * d0 / d1;

  // ---- f1 = f(h0, y0 + h0*f0) -> k[1] ----
  stage_t<1, 1, 0>(h0, 0.f, ycur, i1, v0);
  gridbar(++ep, id);
  gemm_feval(1, row0, col0, kbase, bz, AsBuf, BsBuf);
  gridbar(++ep, id);
  {
    float s = 0.f;
    #pragma unroll
    for (int q = 0; q < 2; q++) {
      int v = v0 + q * NTH;
      float4 y4 = __ldcg(&((const float4*)g_Y[ycur])[v]);
      float4 f0 = ksum2(i1, v);
      float4 f1 = ksum2(1, v);
      float yy[4] = {y4.x, y4.y, y4.z, y4.w};
      float dd[4] = {f1.x - f0.x, f1.y - f0.y, f1.z - f0.z, f1.w - f0.w};
      #pragma unroll
      for (int e = 0; e < 4; e++) {
        float sc = 1e-6f + 1e-3f * fabsf(yy[e]);
        float d = dd[e] / sc;
        s += d * d;
      }
    }
    float S = blockReduce(s, sred);
    if (tid == 0) g_red[2 * NB + id] = S;
  }
  gridbar(++ep, id);
  float d2 = sqrtf(gridSum(2) / (float)N_ELEM) / h0;
  float dmax = fmaxf(d1, d2);
  float h1 = (dmax <= 1e-15f) ? fmaxf(1e-6f, h0 * 1e-3f)
                              : powf(0.01f / dmax, 0.2f);
  float h = fminf(fminf(100.f * h0, h1), 1.0f);
  float t = 0.f;

  // ---- adaptive loop: 13 barriers/step, no commit phase ----
  for (int step = 0; step < 20; step++) {
    float hs = fminf(h, 1.0f - t);

    stage_t<2, 1, 0>(hs, t, ycur, i1, v0); gridbar(++ep, id);
    gemm_feval(1, row0, col0, kbase, bz, AsBuf, BsBuf); gridbar(++ep, id);
    stage_t<3, 2, 0>(hs, t, ycur, i1, v0); gridbar(++ep, id);
    gemm_feval(2, row0, col0, kbase, bz, AsBuf, BsBuf); gridbar(++ep, id);
    stage_t<4, 3, 0>(hs, t, ycur, i1, v0); gridbar(++ep, id);
    gemm_feval(3, row0, col0, kbase, bz, AsBuf, BsBuf); gridbar(++ep, id);
    stage_t<5, 4, 0>(hs, t, ycur, i1, v0); gridbar(++ep, id);
    gemm_feval(4, row0, col0, kbase, bz, AsBuf, BsBuf); gridbar(++ep, id);
    stage_t<6, 5, 0>(hs, t, ycur, i1, v0); gridbar(++ep, id);
    gemm_feval(5, row0, col0, kbase, bz, AsBuf, BsBuf); gridbar(++ep, id);
    stage_t<7, 6, 1>(hs, t, ycur, i1, v0); gridbar(++ep, id);
    gemm_feval(i7, row0, col0, kbase, bz, AsBuf, BsBuf); gridbar(++ep, id);

    int slot = 3 + (step & 1);
    {
      float s = 0.f;
      #pragma unroll
      for (int q = 0; q < 2; q++) {
        int v = v0 + q * NTH;
        float4 k1v = ksum2(i1, v);
        float4 k3v = ksum2(2, v);
        float4 k4v = ksum2(3, v);
        float4 k5v = ksum2(4, v);
        float4 k6v = ksum2(5, v);
        float4 k7v = ksum2(i7, v);
        float4 y4 = __ldcg(&((const float4*)g_Y[ycur])[v]);
        float4 n4 = __ldcg(&((const float4*)g_Y[ycur ^ 1])[v]);
        float e4[4] = {
          ERR_C[0]*k1v.x + ERR_C[1]*k3v.x + ERR_C[2]*k4v.x + ERR_C[3]*k5v.x + ERR_C[4]*k6v.x + ERR_C[5]*k7v.x,
          ERR_C[0]*k1v.y + ERR_C[1]*k3v.y + ERR_C[2]*k4v.y + ERR_C[3]*k5v.y + ERR_C[4]*k6v.y + ERR_C[5]*k7v.y,
          ERR_C[0]*k1v.z + ERR_C[1]*k3v.z + ERR_C[2]*k4v.z + ERR_C[3]*k5v.z + ERR_C[4]*k6v.z + ERR_C[5]*k7v.z,
          ERR_C[0]*k1v.w + ERR_C[1]*k3v.w + ERR_C[2]*k4v.w + ERR_C[3]*k5v.w + ERR_C[4]*k6v.w + ERR_C[5]*k7v.w
        };
        float yy[4] = {y4.x, y4.y, y4.z, y4.w};
        float nn[4] = {n4.x, n4.y, n4.z, n4.w};
        #pragma unroll
        for (int e = 0; e < 4; e++) {
          float sc = 1e-6f + 1e-3f * fmaxf(fabsf(yy[e]), fabsf(nn[e]));
          float d = (e4[e] * hs) / sc;
          s += d * d;
        }
      }
      float S = blockReduce(s, sred);
      if (tid == 0) g_red[slot * NB + id] = S;
    }
    gridbar(++ep, id);
    float en = sqrtf(gridSum(slot) / (float)N_ELEM);

    int accept = en < 1.0f;
    float safe = fmaxf(en, 1e-10f);
    float p = 0.9f * powf(safe, -0.2f);
    float fac = accept ? fminf(10.f, p) : fmaxf(0.2f, p);
    if (accept) {
      t = t + hs;
      int tmp = i1; i1 = i7; i7 = tmp;   // FSAL via index swap
      ycur ^= 1;                          // y via buffer swap
    }
    h = hs * fac;
    if (t >= 1.0f - 1e-7f) break;
  }

  if (id == 0 && tid == 0) g_yfin = ycur;
}

// ---------------- barrier/state init ----------------
__global__ void k_init() {
  if (threadIdx.x < NB) g_flags[threadIdx.x] = 0;
  if (threadIdx.x == 0) g_yfin = 0;
}

// ---------------- C hi/lo split ----------------
__global__ __launch_bounds__(256) void k_prep_C(const float* __restrict__ C) {
  int base = blockIdx.x * 1024 + threadIdx.x;
  #pragma unroll
  for (int r = 0; r < 4; r++) {
    int i = base + r * 256;
    float v = C[i];
    __nv_bfloat16 h = __float2bfloat16(v);
    g_Chi[i] = h;
    g_Clo[i] = __float2bfloat16(v - __bfloat162float(h));
  }
}

// ---------------- GEMM NN (SIMT fp32, 64x32 tiles, grid 16x8) ----------------
__global__ __launch_bounds__(256) void k_gemm_nn(const float* __restrict__ Aext,
                                                const float* __restrict__ Bm,
                                                float* outExt, int mode) {
  const float* A = mode ? g_Y[g_yfin] : Aext;
  float* D = mode ? outExt : g_Y[0];
  const int K = DIM;
  __shared__ float As[16][64];
  __shared__ float Bs[16][32];
  int tid = threadIdx.x;
  int tx = tid & 15, ty = tid >> 4;
  int row0 = blockIdx.y * 64, col0 = blockIdx.x * 32;
  int lr = tid >> 2;
  int lc = (tid & 3) * 4;
  int br = tid >> 4;
  int bc = (tid & 15) * 2;
  float acc[4][2] = {};
  for (int k0 = 0; k0 < K; k0 += 16) {
    float4 av = *(const float4*)&A[(row0 + lr) * K + k0 + lc];
    As[lc+0][lr]=av.x; As[lc+1][lr]=av.y; As[lc+2][lr]=av.z; As[lc+3][lr]=av.w;
    float2 bv = *(const float2*)&Bm[(k0 + br) * DIM + col0 + bc];
    *(float2*)&Bs[br][bc] = bv;
    __syncthreads();
    #pragma unroll
    for (int kk = 0; kk < 16; kk++) {
      float4 a = *(const float4*)&As[kk][ty*4];
      float2 b = *(const float2*)&Bs[kk][tx*2];
      float ar[4] = {a.x,a.y,a.z,a.w};
      #pragma unroll
      for (int i = 0; i < 4; i++) {
        acc[i][0] += ar[i] * b.x;
        acc[i][1] += ar[i] * b.y;
      }
    }
    __syncthreads();
  }
  #pragma unroll
  for (int i = 0; i < 4; i++) {
    float2 o = {acc[i][0], acc[i][1]};
    *(float2*)&D[(row0 + ty*4 + i) * DIM + col0 + tx*2] = o;
  }
}

// ---------------- host launcher ----------------
extern "C" void kernel_launch(void* const* d_in, const int* in_sizes, int n_in,
                              void* d_out, int out_size) {
  const float* x = (const float*)d_in[0];
  const float* P = (const float*)d_in[1];
  const float* C = (const float*)d_in[2];
  const float* F = (const float*)d_in[3];
  float* out = (float*)d_out;

  dim3 gNN(16, 8);

  k_init<<<1, 128>>>();
  k_prep_C<<<512, 256>>>(C);
  k_gemm_nn<<<gNN, 256>>>(x, P, nullptr, 0);     // y0 = x @ P
  k_ode<<<NB, NTH>>>();                          // entire RK45 integration
  k_gemm_nn<<<gNN, 256>>>(nullptr, F, out, 1);   // y_hat = y_f @ F
}

// round 17
// speedup vs baseline: 1.3418x; 1.3418x over previous
#include <cuda_runtime.h>
#include <cuda_bf16.h>
#include <math.h>
#include <stdint.h>

#define DIM   512
#define N_ELEM (DIM*DIM)       // 262144
#define KFLAT 1024             // DT*2
#define NB    128              // persistent CTAs (1/SM)
#define NTH   256

// ---------------- device state ----------------
__device__ float g_Y[2][N_ELEM];       // y double buffer
__device__ float g_K[7][2][N_ELEM];    // k arrays, split-K=2 partials
__device__ __align__(16) __nv_bfloat16 g_bhi[N_ELEM*2];  // basis hi [row][j*2+k]
__device__ __align__(16) __nv_bfloat16 g_blo[N_ELEM*2];  // basis lo
__device__ __align__(16) __nv_bfloat16 g_Chi[DIM*KFLAT]; // C hi (row=out col, K contiguous)
__device__ __align__(16) __nv_bfloat16 g_Clo[DIM*KFLAT]; // C lo
__device__ float g_red[5*NB];
__device__ int   g_bar_cnt;
__device__ int   g_bar_epoch;
__device__ int   g_yfin;

// Dormand-Prince tables
__constant__ float STG_C[8][6] = {
  {0.f,0.f,0.f,0.f,0.f,0.f},
  {1.f,0.f,0.f,0.f,0.f,0.f},
  {0.2f,0.f,0.f,0.f,0.f,0.f},
  {3.f/40.f, 9.f/40.f, 0.f,0.f,0.f,0.f},
  {44.f/45.f, -56.f/15.f, 32.f/9.f, 0.f,0.f,0.f},
  {19372.f/6561.f, -25360.f/2187.f, 64448.f/6561.f, -212.f/729.f,0.f,0.f},
  {9017.f/3168.f, -355.f/33.f, 46732.f/5247.f, 49.f/176.f, -5103.f/18656.f, 0.f},
  {35.f/384.f, 0.f, 500.f/1113.f, 125.f/192.f, -2187.f/6784.f, 11.f/84.f},
};
__constant__ float STG_T[8] = {0.f, 1.f, 0.2f, 0.3f, 0.8f, 8.f/9.f, 1.f, 1.f};
__constant__ float ERR_C[6] = { 71.f/57600.f, -71.f/16695.f, 71.f/1920.f,
                                -17253.f/339200.f, 22.f/525.f, -1.f/40.f };

#define SWZ128(o) ((o) ^ (((o) >> 3) & 0x70))

__device__ __forceinline__ uint32_t smem_u32(const void* p) {
  uint32_t a;
  asm("{ .reg .u64 t; cvta.to.shared.u64 t, %1; cvt.u32.u64 %0, t; }" : "=r"(a) : "l"(p));
  return a;
}

// ---------------- atomic-epoch grid barrier (PROVEN: R10/R13/R14) ----------
__device__ __forceinline__ void gridbar(int* s_epoch) {
  __syncthreads();
  if (threadIdx.x == 0) {
    int e = ++(*s_epoch);
    __threadfence();
    if (atomicAdd(&g_bar_cnt, 1) == NB - 1) {
      g_bar_cnt = 0;
      __threadfence();
      atomicExch(&g_bar_epoch, e);
    } else {
      while (*((volatile int*)&g_bar_epoch) < e) { }
    }
    __threadfence();
  }
  __syncthreads();
}

// ---------------- basis pack helper ----------------
__device__ __forceinline__ void basis_pack(float ph, uint32_t& h, uint32_t& l) {
  float s, c;
  sincosf(ph, &s, &c);
  __nv_bfloat16 sh = __float2bfloat16(s);
  __nv_bfloat16 ch = __float2bfloat16(c);
  __nv_bfloat162 hp(sh, ch);
  __nv_bfloat162 lp(__float2bfloat16(s - __bfloat162float(sh)),
                    __float2bfloat16(c - __bfloat162float(ch)));
  h = *(uint32_t*)&hp;
  l = *(uint32_t*)&lp;
}

// sum of split partials, vectorized
__device__ __forceinline__ float4 ksum2(int kidx, int v) {
  float4 a = __ldcg(&((const float4*)g_K[kidx][0])[v]);
  float4 b = __ldcg(&((const float4*)g_K[kidx][1])[v]);
  return make_float4(a.x + b.x, a.y + b.y, a.z + b.z, a.w + b.w);
}

// ---------------- vectorized, specialized stage ----------------
template<int SID, int NK, int WRITEY>
__device__ __forceinline__ void stage_v(float hs, float t, int ycur, int i1, int v) {
  float ts = t + STG_T[SID] * hs;
  float4 y4 = __ldcg(&((const float4*)g_Y[ycur])[v]);
  float ax = 0.f, ay = 0.f, az = 0.f, aw = 0.f;
  #pragma unroll
  for (int j = 0; j < NK; j++) {
    int kidx = (j == 0) ? i1 : j;
    float cj = STG_C[SID][j];
    float4 k0 = __ldcg(&((const float4*)g_K[kidx][0])[v]);
    float4 k1 = __ldcg(&((const float4*)g_K[kidx][1])[v]);
    ax += cj * (k0.x + k1.x);
    ay += cj * (k0.y + k1.y);
    az += cj * (k0.z + k1.z);
    aw += cj * (k0.w + k1.w);
  }
  float yt0 = y4.x, yt1 = y4.y, yt2 = y4.z, yt3 = y4.w;
  if (NK > 0) { yt0 += hs * ax; yt1 += hs * ay; yt2 += hs * az; yt3 += hs * aw; }
  if (WRITEY) ((float4*)g_Y[ycur ^ 1])[v] = make_float4(yt0, yt1, yt2, yt3);
  uint4 H, L;
  basis_pack(yt0 + ts, H.x, L.x);
  basis_pack(yt1 + ts, H.y, L.y);
  basis_pack(yt2 + ts, H.z, L.z);
  basis_pack(yt3 + ts, H.w, L.w);
  ((uint4*)g_bhi)[v] = H;
  ((uint4*)g_blo)[v] = L;
}

template<int SID, int NK, int WRITEY>
__device__ __forceinline__ void stage_t(float hs, float t, int ycur, int i1, int v0) {
  stage_v<SID, NK, WRITEY>(hs, t, ycur, i1, v0);
  stage_v<SID, NK, WRITEY>(hs, t, ycur, i1, v0 + NTH);
}

// ---------------- bf16 mma GEMM NT (round-10 champion, verbatim logic) ------
__device__ __forceinline__ void mma_bf16(float* c, uint32_t a0, uint32_t a1,
                                         uint32_t a2, uint32_t a3,
                                         uint32_t b0, uint32_t b1) {
  asm volatile("mma.sync.aligned.m16n8k16.row.col.f32.bf16.bf16.f32 "
               "{%0,%1,%2,%3}, {%4,%5,%6,%7}, {%8,%9}, {%0,%1,%2,%3};"
               : "+f"(c[0]), "+f"(c[1]), "+f"(c[2]), "+f"(c[3])
               : "r"(a0), "r"(a1), "r"(a2), "r"(a3), "r"(b0), "r"(b1));
}

#define TILE_B 8192   // 64 rows x 128 bytes

__device__ void gemm_feval(int dst, int row0, int col0, int kbase, int bz,
                           char* AsBuf, char* BsBuf) {
  float* D = &g_K[dst][bz][0];
  int tid = threadIdx.x, wid = tid >> 5, lane = tid & 31;
  int wr = wid >> 2, wc = wid & 3;         // warp grid 2x4: tile 32x16

  int lrow0 = tid >> 3, lch0 = tid & 7;
  int c1i = tid + 256;
  int lrow1 = c1i >> 3, lch1 = c1i & 7;
  uint32_t so0 = SWZ128((uint32_t)(lrow0 * 128 + lch0 * 16));
  uint32_t so1 = SWZ128((uint32_t)(lrow1 * 128 + lch1 * 16));

  int g = lane >> 3, r = lane & 7;
  int a_m = ((g & 1) ? 8 : 0) + r;
  int a_k = (g >> 1) * 8;
  int b_n = ((g >> 1) ? 8 : 0) + r;
  int b_k = (g & 1) * 8;

  uint32_t Asm = smem_u32(AsBuf), Bsm = smem_u32(BsBuf);
  float acc[2][2][4] = {};

  // prologue: chunk 0 -> buffer 0
  {
    const __nv_bfloat16* As = g_bhi;
    const __nv_bfloat16* Bs = g_Chi;
    *(uint4*)(AsBuf + so0) = __ldcg((const uint4*)&As[(size_t)(row0 + lrow0) * KFLAT + kbase + lch0 * 8]);
    *(uint4*)(AsBuf + so1) = __ldcg((const uint4*)&As[(size_t)(row0 + lrow1) * KFLAT + kbase + lch1 * 8]);
    *(uint4*)(BsBuf + so0) = __ldcg((const uint4*)&Bs[(size_t)(col0 + lrow0) * KFLAT + kbase + lch0 * 8]);
    *(uint4*)(BsBuf + so1) = __ldcg((const uint4*)&Bs[(size_t)(col0 + lrow1) * KFLAT + kbase + lch1 * 8]);
  }
  __syncthreads();

  int cur = 0;
  for (int tk = 0; tk < 24; tk++) {
    uint4 av0, av1, bv0, bv1;
    if (tk < 23) {
      int nt = tk + 1, seg = nt >> 3;
      const __nv_bfloat16* As = (seg == 2) ? g_blo : g_bhi;
      const __nv_bfloat16* Bs = (seg == 1) ? g_Clo : g_Chi;
      int koff = kbase + (nt & 7) * 64;
      av0 = __ldcg((const uint4*)&As[(size_t)(row0 + lrow0) * KFLAT + koff + lch0 * 8]);
      av1 = __ldcg((const uint4*)&As[(size_t)(row0 + lrow1) * KFLAT + koff + lch1 * 8]);
      bv0 = __ldcg((const uint4*)&Bs[(size_t)(col0 + lrow0) * KFLAT + koff + lch0 * 8]);
      bv1 = __ldcg((const uint4*)&Bs[(size_t)(col0 + lrow1) * KFLAT + koff + lch1 * 8]);
    }
    uint32_t Ab = Asm + cur * TILE_B, Bb = Bsm + cur * TILE_B;
    #pragma unroll
    for (int s = 0; s < 4; s++) {
      uint32_t b0, b1, b2, b3;
      uint32_t addrB = Bb + SWZ128((uint32_t)((wc * 16 + b_n) * 128 + (s * 16 + b_k) * 2));
      asm volatile("ldmatrix.sync.aligned.m8n8.x4.shared.b16 {%0,%1,%2,%3}, [%4];"
                   : "=r"(b0), "=r"(b1), "=r"(b2), "=r"(b3) : "r"(addrB));
      #pragma unroll
      for (int mf = 0; mf < 2; mf++) {
        uint32_t a0, a1, a2, a3;
        uint32_t addrA = Ab + SWZ128((uint32_t)((wr * 32 + mf * 16 + a_m) * 128 + (s * 16 + a_k) * 2));
        asm volatile("ldmatrix.sync.aligned.m8n8.x4.shared.b16 {%0,%1,%2,%3}, [%4];"
                     : "=r"(a0), "=r"(a1), "=r"(a2), "=r"(a3) : "r"(addrA));
        mma_bf16(acc[mf][0], a0, a1, a2, a3, b0, b1);
        mma_bf16(acc[mf][1], a0, a1, a2, a3, b2, b3);
      }
    }
    if (tk < 23) {
      int nxt = cur ^ 1;
      *(uint4*)(AsBuf + nxt * TILE_B + so0) = av0;
      *(uint4*)(AsBuf + nxt * TILE_B + so1) = av1;
      *(uint4*)(BsBuf + nxt * TILE_B + so0) = bv0;
      *(uint4*)(BsBuf + nxt * TILE_B + so1) = bv1;
      __syncthreads();
      cur = nxt;
    }
  }

  int mrow = row0 + wr * 32 + (lane >> 2);
  int ncol = col0 + wc * 16 + (lane & 3) * 2;
  #pragma unroll
  for (int mf = 0; mf < 2; mf++) {
    #pragma unroll
    for (int nf = 0; nf < 2; nf++) {
      float2 lo = {acc[mf][nf][0], acc[mf][nf][1]};
      float2 hi = {acc[mf][nf][2], acc[mf][nf][3]};
      *(float2*)&D[(size_t)(mrow + mf * 16)     * DIM + ncol + nf * 8] = lo;
      *(float2*)&D[(size_t)(mrow + mf * 16 + 8) * DIM + ncol + nf * 8] = hi;
    }
  }
  __syncthreads();
}

// ---------------- block reduce ----------------
__device__ __forceinline__ float blockReduce(float v, float* sh) {
  int tid = threadIdx.x;
  sh[tid] = v; __syncthreads();
  for (int s = 128; s > 0; s >>= 1) {
    if (tid < s) sh[tid] += sh[tid + s];
    __syncthreads();
  }
  float r = sh[0];
  __syncthreads();
  return r;
}

__device__ __forceinline__ float gridSum(int slot) {
  float S = 0.f;
  for (int b = 0; b < NB; b++) S += __ldcg(&g_red[slot * NB + b]);
  return S;
}

// squared scaled norm of one float4 pair (y, f)
__device__ __forceinline__ void norm_acc(float4 y4, float4 f4, float& s0, float& s1) {
  float yy[4] = {y4.x, y4.y, y4.z, y4.w};
  float ff[4] = {f4.x, f4.y, f4.z, f4.w};
  #pragma unroll
  for (int e = 0; e < 4; e++) {
    float sc = 1e-6f + 1e-3f * fabsf(yy[e]);
    float a = yy[e] / sc, b = ff[e] / sc;
    s0 += a * a; s1 += b * b;
  }
}

// ---------------- persistent ODE kernel ----------------
__global__ __launch_bounds__(NTH, 1) void k_ode() {
  __shared__ __align__(16) char AsBuf[2 * TILE_B];
  __shared__ __align__(16) char BsBuf[2 * TILE_B];
  __shared__ float sred[NTH];
  __shared__ int   s_epoch;
  int tid = threadIdx.x, id = blockIdx.x;
  int bx = id & 7, by = (id >> 3) & 7, bz = id >> 6;
  int row0 = by * 64, col0 = bx * 64, kbase = bz * 512;
  int v0 = id * 512 + tid;        // this thread's two float4s: v0, v0+256
  if (tid == 0) s_epoch = 0;
  __syncthreads();

  int ycur = 0, i1 = 0, i7 = 6;

  // ---- f0 = f(0, y0) -> k[i1] ----
  stage_t<0, 0, 0>(0.f, 0.f, ycur, i1, v0);
  gridbar(&s_epoch);
  gemm_feval(i1, row0, col0, kbase, bz, AsBuf, BsBuf);
  gridbar(&s_epoch);

  // ---- d0, d1 ----
  {
    float s0 = 0.f, s1 = 0.f;
    #pragma unroll
    for (int q = 0; q < 2; q++) {
      int v = v0 + q * NTH;
      float4 y4 = __ldcg(&((const float4*)g_Y[ycur])[v]);
      float4 f4 = ksum2(i1, v);
      norm_acc(y4, f4, s0, s1);
    }
    float S0 = blockReduce(s0, sred);
    float S1 = blockReduce(s1, sred);
    if (tid == 0) { g_red[0 * NB + id] = S0; g_red[1 * NB + id] = S1; }
  }
  gridbar(&s_epoch);
  float d0 = sqrtf(gridSum(0) / (float)N_ELEM);
  float d1 = sqrtf(gridSum(1) / (float)N_ELEM);
  float h0 = (d0 < 1e-5f || d1 < 1e-5f) ? 1e-6f : 0.01f * d0 / d1;

  // ---- f1 = f(h0, y0 + h0*f0) -> k[1] ----
  stage_t<1, 1, 0>(h0, 0.f, ycur, i1, v0);
  gridbar(&s_epoch);
  gemm_feval(1, row0, col0, kbase, bz, AsBuf, BsBuf);
  gridbar(&s_epoch);
  {
    float s = 0.f;
    #pragma unroll
    for (int q = 0; q < 2; q++) {
      int v = v0 + q * NTH;
      float4 y4 = __ldcg(&((const float4*)g_Y[ycur])[v]);
      float4 f0 = ksum2(i1, v);
      float4 f1 = ksum2(1, v);
      float yy[4] = {y4.x, y4.y, y4.z, y4.w};
      float dd[4] = {f1.x - f0.x, f1.y - f0.y, f1.z - f0.z, f1.w - f0.w};
      #pragma unroll
      for (int e = 0; e < 4; e++) {
        float sc = 1e-6f + 1e-3f * fabsf(yy[e]);
        float d = dd[e] / sc;
        s += d * d;
      }
    }
    float S = blockReduce(s, sred);
    if (tid == 0) g_red[2 * NB + id] = S;
  }
  gridbar(&s_epoch);
  float d2 = sqrtf(gridSum(2) / (float)N_ELEM) / h0;
  float dmax = fmaxf(d1, d2);
  float h1 = (dmax <= 1e-15f) ? fmaxf(1e-6f, h0 * 1e-3f)
                              : powf(0.01f / dmax, 0.2f);
  float h = fminf(fminf(100.f * h0, h1), 1.0f);
  float t = 0.f;

  // ---- adaptive loop: 13 barriers/step, no commit phase ----
  for (int step = 0; step < 20; step++) {
    float hs = fminf(h, 1.0f - t);

    stage_t<2, 1, 0>(hs, t, ycur, i1, v0); gridbar(&s_epoch);
    gemm_feval(1, row0, col0, kbase, bz, AsBuf, BsBuf); gridbar(&s_epoch);
    stage_t<3, 2, 0>(hs, t, ycur, i1, v0); gridbar(&s_epoch);
    gemm_feval(2, row0, col0, kbase, bz, AsBuf, BsBuf); gridbar(&s_epoch);
    stage_t<4, 3, 0>(hs, t, ycur, i1, v0); gridbar(&s_epoch);
    gemm_feval(3, row0, col0, kbase, bz, AsBuf, BsBuf); gridbar(&s_epoch);
    stage_t<5, 4, 0>(hs, t, ycur, i1, v0); gridbar(&s_epoch);
    gemm_feval(4, row0, col0, kbase, bz, AsBuf, BsBuf); gridbar(&s_epoch);
    stage_t<6, 5, 0>(hs, t, ycur, i1, v0); gridbar(&s_epoch);
    gemm_feval(5, row0, col0, kbase, bz, AsBuf, BsBuf); gridbar(&s_epoch);
    stage_t<7, 6, 1>(hs, t, ycur, i1, v0); gridbar(&s_epoch);
    gemm_feval(i7, row0, col0, kbase, bz, AsBuf, BsBuf); gridbar(&s_epoch);

    int slot = 3 + (step & 1);
    {
      float s = 0.f;
      #pragma unroll
      for (int q = 0; q < 2; q++) {
        int v = v0 + q * NTH;
        float4 k1v = ksum2(i1, v);
        float4 k3v = ksum2(2, v);
        float4 k4v = ksum2(3, v);
        float4 k5v = ksum2(4, v);
        float4 k6v = ksum2(5, v);
        float4 k7v = ksum2(i7, v);
        float4 y4 = __ldcg(&((const float4*)g_Y[ycur])[v]);
        float4 n4 = __ldcg(&((const float4*)g_Y[ycur ^ 1])[v]);
        float e4[4] = {
          ERR_C[0]*k1v.x + ERR_C[1]*k3v.x + ERR_C[2]*k4v.x + ERR_C[3]*k5v.x + ERR_C[4]*k6v.x + ERR_C[5]*k7v.x,
          ERR_C[0]*k1v.y + ERR_C[1]*k3v.y + ERR_C[2]*k4v.y + ERR_C[3]*k5v.y + ERR_C[4]*k6v.y + ERR_C[5]*k7v.y,
          ERR_C[0]*k1v.z + ERR_C[1]*k3v.z + ERR_C[2]*k4v.z + ERR_C[3]*k5v.z + ERR_C[4]*k6v.z + ERR_C[5]*k7v.z,
          ERR_C[0]*k1v.w + ERR_C[1]*k3v.w + ERR_C[2]*k4v.w + ERR_C[3]*k5v.w + ERR_C[4]*k6v.w + ERR_C[5]*k7v.w
        };
        float yy[4] = {y4.x, y4.y, y4.z, y4.w};
        float nn[4] = {n4.x, n4.y, n4.z, n4.w};
        #pragma unroll
        for (int e = 0; e < 4; e++) {
          float sc = 1e-6f + 1e-3f * fmaxf(fabsf(yy[e]), fabsf(nn[e]));
          float d = (e4[e] * hs) / sc;
          s += d * d;
        }
      }
      float S = blockReduce(s, sred);
      if (tid == 0) g_red[slot * NB + id] = S;
    }
    gridbar(&s_epoch);
    float en = sqrtf(gridSum(slot) / (float)N_ELEM);

    int accept = en < 1.0f;
    float safe = fmaxf(en, 1e-10f);
    float p = 0.9f * powf(safe, -0.2f);
    float fac = accept ? fminf(10.f, p) : fmaxf(0.2f, p);
    if (accept) {
      t = t + hs;
      int tmp = i1; i1 = i7; i7 = tmp;   // FSAL via index swap
      ycur ^= 1;                          // y via buffer swap
    }
    h = hs * fac;
    if (t >= 1.0f - 1e-7f) break;
  }

  if (id == 0 && tid == 0) g_yfin = ycur;
}

// ---------------- barrier/state init ----------------
__global__ void k_init() { g_bar_cnt = 0; g_bar_epoch = 0; g_yfin = 0; }

// ---------------- C hi/lo split ----------------
__global__ __launch_bounds__(256) void k_prep_C(const float* __restrict__ C) {
  int base = blockIdx.x * 1024 + threadIdx.x;
  #pragma unroll
  for (int r = 0; r < 4; r++) {
    int i = base + r * 256;
    float v = C[i];
    __nv_bfloat16 h = __float2bfloat16(v);
    g_Chi[i] = h;
    g_Clo[i] = __float2bfloat16(v - __bfloat162float(h));
  }
}

// ---------------- GEMM NN (SIMT fp32, 64x32 tiles, grid 16x8) ----------------
__global__ __launch_bounds__(256) void k_gemm_nn(const float* __restrict__ Aext,
                                                const float* __restrict__ Bm,
                                                float* outExt, int mode) {
  const float* A = mode ? g_Y[g_yfin] : Aext;
  float* D = mode ? outExt : g_Y[0];
  const int K = DIM;
  __shared__ float As[16][64];
  __shared__ float Bs[16][32];
  int tid = threadIdx.x;
  int tx = tid & 15, ty = tid >> 4;
  int row0 = blockIdx.y * 64, col0 = blockIdx.x * 32;
  int lr = tid >> 2;
  int lc = (tid & 3) * 4;
  int br = tid >> 4;
  int bc = (tid & 15) * 2;
  float acc[4][2] = {};
  for (int k0 = 0; k0 < K; k0 += 16) {
    float4 av = *(const float4*)&A[(row0 + lr) * K + k0 + lc];
    As[lc+0][lr]=av.x; As[lc+1][lr]=av.y; As[lc+2][lr]=av.z; As[lc+3][lr]=av.w;
    float2 bv = *(const float2*)&Bm[(k0 + br) * DIM + col0 + bc];
    *(float2*)&Bs[br][bc] = bv;
    __syncthreads();
    #pragma unroll
    for (int kk = 0; kk < 16; kk++) {
      float4 a = *(const float4*)&As[kk][ty*4];
      float2 b = *(const float2*)&Bs[kk][tx*2];
      float ar[4] = {a.x,a.y,a.z,a.w};
      #pragma unroll
      for (int i = 0; i < 4; i++) {
        acc[i][0] += ar[i] * b.x;
        acc[i][1] += ar[i] * b.y;
      }
    }
    __syncthreads();
  }
  #pragma unroll
  for (int i = 0; i < 4; i++) {
    float2 o = {acc[i][0], acc[i][1]};
    *(float2*)&D[(row0 + ty*4 + i) * DIM + col0 + tx*2] = o;
  }
}

// ---------------- host launcher ----------------
extern "C" void kernel_launch(void* const* d_in, const int* in_sizes, int n_in,
                              void* d_out, int out_size) {
  const float* x = (const float*)d_in[0];
  const float* P = (const float*)d_in[1];
  const float* C = (const float*)d_in[2];
  const float* F = (const float*)d_in[3];
  float* out = (float*)d_out;

  dim3 gNN(16, 8);

  k_init<<<1, 1>>>();
  k_prep_C<<<512, 256>>>(C);
  k_gemm_nn<<<gNN, 256>>>(x, P, nullptr, 0);     // y0 = x @ P
  k_ode<<<NB, NTH>>>();                          // entire RK45 integration
  k_gemm_nn<<<gNN, 256>>>(nullptr, F, out, 1);   // y_hat = y_f @ F
}